// round 1
// baseline (speedup 1.0000x reference)
#include <cuda_runtime.h>

#define NBLK 2048
#define TPB  256
#define NWARP (TPB / 32)
static constexpr int BATCH = 16777216;   // 2^24

// Deterministic per-block partials (no float atomics -> identical result every replay)
__device__ float    g_sums[5][NBLK];
__device__ unsigned g_cnts[5][NBLK];

__device__ __forceinline__ float warp_red_f(float v) {
#pragma unroll
    for (int o = 16; o; o >>= 1) v += __shfl_down_sync(0xffffffffu, v, o);
    return v;
}
__device__ __forceinline__ unsigned warp_red_u(unsigned v) {
#pragma unroll
    for (int o = 16; o; o >>= 1) v += __shfl_down_sync(0xffffffffu, v, o);
    return v;
}

__global__ __launch_bounds__(TPB) void amp_reduce(
    const float4* __restrict__ dbp,   // dbp_pred
    const float4* __restrict__ sbp,   // sbp_pred (squeezed [B,1] -> [B])
    const float4* __restrict__ dt,    // d targets
    const float4* __restrict__ st)    // s targets
{
    float    sum[5] = {0.f, 0.f, 0.f, 0.f, 0.f};
    unsigned cnt[5] = {0u, 0u, 0u, 0u, 0u};

    const int n4 = BATCH / 4;
    for (int i = blockIdx.x * TPB + threadIdx.x; i < n4; i += NBLK * TPB) {
        const float4 s4  = __ldg(st  + i);
        const float4 d4  = __ldg(dt  + i);
        const float4 dp4 = __ldg(dbp + i);
        const float4 sp4 = __ldg(sbp + i);

        const float sa[4] = {s4.x,  s4.y,  s4.z,  s4.w};
        const float da[4] = {d4.x,  d4.y,  d4.z,  d4.w};
        const float pa[4] = {dp4.x, dp4.y, dp4.z, dp4.w};
        const float qa[4] = {sp4.x, sp4.y, sp4.z, sp4.w};

#pragma unroll
        for (int j = 0; j < 4; j++) {
            const float s  = sa[j];
            const float d  = da[j];
            const float pd = pa[j];
            const float ps = qa[j];

            // per_elem = smape(dbp_pred, d) + smape(sbp_pred, s)
            const float pe = 2.0f * fabsf(pd - d) / (fabsf(pd) + fabsf(d))
                           + 2.0f * fabsf(ps - s) / (fabsf(ps) + fabsf(s));

            const bool normal   = (s < 120.f) && (d < 80.f);
            const bool elevated = (s >= 120.f) && (s < 130.f) && (d < 80.f) && !normal;
            const bool hyper1   = (((s >= 130.f) && (s < 140.f)) ||
                                   ((d >= 80.f) && (d < 90.f))) && !(normal || elevated);
            const bool hyper2   = ((s >= 140.f) || (d >= 90.f)) &&
                                  !(normal || elevated || hyper1);
            const bool crisis   = (s > 180.f) || (d > 120.f);  // intentionally not exclusive

            sum[0] += normal   ? pe : 0.f;  cnt[0] += (unsigned)normal;
            sum[1] += elevated ? pe : 0.f;  cnt[1] += (unsigned)elevated;
            sum[2] += hyper1   ? pe : 0.f;  cnt[2] += (unsigned)hyper1;
            sum[3] += hyper2   ? pe : 0.f;  cnt[3] += (unsigned)hyper2;
            sum[4] += crisis   ? pe : 0.f;  cnt[4] += (unsigned)crisis;
        }
    }

    // Block reduction: warp shuffle, then cross-warp via shared.
    __shared__ float    ws[5][NWARP];
    __shared__ unsigned wc[5][NWARP];
    const int lane = threadIdx.x & 31;
    const int warp = threadIdx.x >> 5;

#pragma unroll
    for (int m = 0; m < 5; m++) {
        const float    fs = warp_red_f(sum[m]);
        const unsigned uc = warp_red_u(cnt[m]);
        if (lane == 0) { ws[m][warp] = fs; wc[m][warp] = uc; }
    }
    __syncthreads();

    if (warp == 0) {
#pragma unroll
        for (int m = 0; m < 5; m++) {
            float    fs = (lane < NWARP) ? ws[m][lane] : 0.f;
            unsigned uc = (lane < NWARP) ? wc[m][lane] : 0u;
#pragma unroll
            for (int o = NWARP / 2; o; o >>= 1) {
                fs += __shfl_down_sync(0xffffffffu, fs, o);
                uc += __shfl_down_sync(0xffffffffu, uc, o);
            }
            if (lane == 0) {
                g_sums[m][blockIdx.x] = fs;
                g_cnts[m][blockIdx.x] = uc;
            }
        }
    }
}

__global__ __launch_bounds__(256) void amp_finalize(float* __restrict__ out)
{
    float    sum[5] = {0.f, 0.f, 0.f, 0.f, 0.f};
    unsigned cnt[5] = {0u, 0u, 0u, 0u, 0u};

    for (int b = threadIdx.x; b < NBLK; b += 256) {
#pragma unroll
        for (int m = 0; m < 5; m++) {
            sum[m] += g_sums[m][b];
            cnt[m] += g_cnts[m][b];
        }
    }

    __shared__ float    ws[5][8];
    __shared__ unsigned wc[5][8];
    __shared__ float    fsum[5];
    __shared__ unsigned fcnt[5];
    const int lane = threadIdx.x & 31;
    const int warp = threadIdx.x >> 5;

#pragma unroll
    for (int m = 0; m < 5; m++) {
        const float    fs = warp_red_f(sum[m]);
        const unsigned uc = warp_red_u(cnt[m]);
        if (lane == 0) { ws[m][warp] = fs; wc[m][warp] = uc; }
    }
    __syncthreads();

    if (warp == 0) {
#pragma unroll
        for (int m = 0; m < 5; m++) {
            float    fs = (lane < 8) ? ws[m][lane] : 0.f;
            unsigned uc = (lane < 8) ? wc[m][lane] : 0u;
#pragma unroll
            for (int o = 4; o; o >>= 1) {
                fs += __shfl_down_sync(0xffffffffu, fs, o);
                uc += __shfl_down_sync(0xffffffffu, uc, o);
            }
            if (lane == 0) { fsum[m] = fs; fcnt[m] = uc; }
        }
    }
    __syncthreads();

    if (threadIdx.x == 0) {
        float rst = 0.f, m_rst = 0.f, mask_cnt = 0.f;
#pragma unroll
        for (int m = 0; m < 5; m++) {
            const float c = (float)fcnt[m];
            const float w = sqrtf(logf((float)BATCH / fmaxf(c, 1.0f)));
            const float S = fsum[m] * w;
            if (c > 0.f) {
                m_rst = (m_rst + S) / c / 2.0f;
                rst += m_rst;
                mask_cnt += 1.0f;
            }
        }
        out[0] = (mask_cnt == 0.f) ? (rst / 5.0f) : (rst / mask_cnt);
    }
}

extern "C" void kernel_launch(void* const* d_in, const int* in_sizes, int n_in,
                              void* d_out, int out_size)
{
    // metadata order: dbp_pred, sbp_pred, mbp_pred, d, s, m
    const float* dbp = (const float*)d_in[0];
    const float* sbp = (const float*)d_in[1];
    const float* dt  = (const float*)d_in[3];
    const float* st  = (const float*)d_in[4];

    amp_reduce<<<NBLK, TPB>>>((const float4*)dbp, (const float4*)sbp,
                              (const float4*)dt,  (const float4*)st);
    amp_finalize<<<1, 256>>>((float*)d_out);
}

// round 2
// speedup vs baseline: 1.0005x; 1.0005x over previous
#include <cuda_runtime.h>

#define NBLK 2048
#define TPB  256
#define NWARP (TPB / 32)
static constexpr int BATCH = 16777216;   // 2^24
static constexpr int N4    = BATCH / 4;  // float4 elements
// N4 / (NBLK*TPB) == 8 exactly -> fixed trip count, no bounds checks

// Deterministic per-block partials (no float atomics -> identical every replay)
__device__ float    g_sums[5][NBLK];
__device__ unsigned g_cnts[5][NBLK];
__device__ unsigned g_ticket;   // zero-initialized; last block resets it each launch

__device__ __forceinline__ float warp_red_f(float v) {
#pragma unroll
    for (int o = 16; o; o >>= 1) v += __shfl_down_sync(0xffffffffu, v, o);
    return v;
}
__device__ __forceinline__ unsigned warp_red_u(unsigned v) {
#pragma unroll
    for (int o = 16; o; o >>= 1) v += __shfl_down_sync(0xffffffffu, v, o);
    return v;
}

struct Acc {
    float    sum[5];
    unsigned cnt[5];
};

__device__ __forceinline__ void process4(Acc& a,
                                         const float4 s4, const float4 d4,
                                         const float4 dp4, const float4 sp4)
{
    const float sa[4] = {s4.x,  s4.y,  s4.z,  s4.w};
    const float da[4] = {d4.x,  d4.y,  d4.z,  d4.w};
    const float pa[4] = {dp4.x, dp4.y, dp4.z, dp4.w};
    const float qa[4] = {sp4.x, sp4.y, sp4.z, sp4.w};

#pragma unroll
    for (int j = 0; j < 4; j++) {
        const float s  = sa[j];
        const float d  = da[j];
        const float pd = pa[j];
        const float ps = qa[j];

        // per_elem = smape(dbp_pred, d) + smape(sbp_pred, s); fast divide is
        // well within the 1e-3 rel-err budget and deterministic across replays
        const float pe = 2.0f * __fdividef(fabsf(pd - d), fabsf(pd) + fabsf(d))
                       + 2.0f * __fdividef(fabsf(ps - s), fabsf(ps) + fabsf(s));

        const bool normal   = (s < 120.f) && (d < 80.f);
        const bool elevated = (s >= 120.f) && (s < 130.f) && (d < 80.f) && !normal;
        const bool hyper1   = (((s >= 130.f) && (s < 140.f)) ||
                               ((d >= 80.f) && (d < 90.f))) && !(normal || elevated);
        const bool hyper2   = ((s >= 140.f) || (d >= 90.f)) &&
                              !(normal || elevated || hyper1);
        const bool crisis   = (s > 180.f) || (d > 120.f);  // intentionally overlapping

        a.sum[0] += normal   ? pe : 0.f;  a.cnt[0] += (unsigned)normal;
        a.sum[1] += elevated ? pe : 0.f;  a.cnt[1] += (unsigned)elevated;
        a.sum[2] += hyper1   ? pe : 0.f;  a.cnt[2] += (unsigned)hyper1;
        a.sum[3] += hyper2   ? pe : 0.f;  a.cnt[3] += (unsigned)hyper2;
        a.sum[4] += crisis   ? pe : 0.f;  a.cnt[4] += (unsigned)crisis;
    }
}

__global__ __launch_bounds__(TPB) void amp_fused(
    const float4* __restrict__ dbp,
    const float4* __restrict__ sbp,
    const float4* __restrict__ dt,
    const float4* __restrict__ st,
    float* __restrict__ out)
{
    Acc a;
#pragma unroll
    for (int m = 0; m < 5; m++) { a.sum[m] = 0.f; a.cnt[m] = 0u; }

    const int stride = NBLK * TPB;
    const int base   = blockIdx.x * TPB + threadIdx.x;

    // Exactly 8 iterations per thread; unroll 2 -> 8 independent LDG.128 in flight.
#pragma unroll 2
    for (int k = 0; k < 8; k++) {
        const int i = base + k * stride;
        const float4 s4  = __ldg(st  + i);
        const float4 d4  = __ldg(dt  + i);
        const float4 dp4 = __ldg(dbp + i);
        const float4 sp4 = __ldg(sbp + i);
        process4(a, s4, d4, dp4, sp4);
    }

    // ---- block reduction ----
    __shared__ float    ws[5][NWARP];
    __shared__ unsigned wc[5][NWARP];
    const int lane = threadIdx.x & 31;
    const int warp = threadIdx.x >> 5;

#pragma unroll
    for (int m = 0; m < 5; m++) {
        const float    fs = warp_red_f(a.sum[m]);
        const unsigned uc = warp_red_u(a.cnt[m]);
        if (lane == 0) { ws[m][warp] = fs; wc[m][warp] = uc; }
    }
    __syncthreads();

    if (warp == 0) {
#pragma unroll
        for (int m = 0; m < 5; m++) {
            float    fs = (lane < NWARP) ? ws[m][lane] : 0.f;
            unsigned uc = (lane < NWARP) ? wc[m][lane] : 0u;
#pragma unroll
            for (int o = NWARP / 2; o; o >>= 1) {
                fs += __shfl_down_sync(0xffffffffu, fs, o);
                uc += __shfl_down_sync(0xffffffffu, uc, o);
            }
            if (lane == 0) {
                g_sums[m][blockIdx.x] = fs;
                g_cnts[m][blockIdx.x] = uc;
            }
        }
    }

    // ---- last-block finalize (fused; kills the 10us second kernel) ----
    __shared__ bool s_last;
    __threadfence();
    __syncthreads();
    if (threadIdx.x == 0)
        s_last = (atomicAdd(&g_ticket, 1u) == (unsigned)(NBLK - 1));
    __syncthreads();
    if (!s_last) return;

    __threadfence();  // acquire: make all blocks' partials visible

    float    fsum5[5] = {0.f, 0.f, 0.f, 0.f, 0.f};
    unsigned fcnt5[5] = {0u, 0u, 0u, 0u, 0u};
#pragma unroll
    for (int k = 0; k < NBLK / TPB; k++) {
        const int b = threadIdx.x + k * TPB;
#pragma unroll
        for (int m = 0; m < 5; m++) {
            fsum5[m] += g_sums[m][b];
            fcnt5[m] += g_cnts[m][b];
        }
    }

    __shared__ float    fsum[5];
    __shared__ unsigned fcnt[5];
#pragma unroll
    for (int m = 0; m < 5; m++) {
        const float    fs = warp_red_f(fsum5[m]);
        const unsigned uc = warp_red_u(fcnt5[m]);
        if (lane == 0) { ws[m][warp] = fs; wc[m][warp] = uc; }
    }
    __syncthreads();

    if (warp == 0) {
#pragma unroll
        for (int m = 0; m < 5; m++) {
            float    fs = (lane < NWARP) ? ws[m][lane] : 0.f;
            unsigned uc = (lane < NWARP) ? wc[m][lane] : 0u;
#pragma unroll
            for (int o = NWARP / 2; o; o >>= 1) {
                fs += __shfl_down_sync(0xffffffffu, fs, o);
                uc += __shfl_down_sync(0xffffffffu, uc, o);
            }
            if (lane == 0) { fsum[m] = fs; fcnt[m] = uc; }
        }
    }
    __syncthreads();

    if (threadIdx.x == 0) {
        float rst = 0.f, m_rst = 0.f, mask_cnt = 0.f;
#pragma unroll
        for (int m = 0; m < 5; m++) {
            const float c = (float)fcnt[m];
            const float w = sqrtf(logf((float)BATCH / fmaxf(c, 1.0f)));
            const float S = fsum[m] * w;
            if (c > 0.f) {
                m_rst = (m_rst + S) / c / 2.0f;
                rst += m_rst;
                mask_cnt += 1.0f;
            }
        }
        out[0] = (mask_cnt == 0.f) ? (rst / 5.0f) : (rst / mask_cnt);
        g_ticket = 0u;   // reset for next graph replay
    }
}

extern "C" void kernel_launch(void* const* d_in, const int* in_sizes, int n_in,
                              void* d_out, int out_size)
{
    // metadata order: dbp_pred, sbp_pred, mbp_pred, d, s, m
    const float* dbp = (const float*)d_in[0];
    const float* sbp = (const float*)d_in[1];
    const float* dt  = (const float*)d_in[3];
    const float* st  = (const float*)d_in[4];

    amp_fused<<<NBLK, TPB>>>((const float4*)dbp, (const float4*)sbp,
                             (const float4*)dt,  (const float4*)st,
                             (float*)d_out);
}

// round 3
// speedup vs baseline: 1.1289x; 1.1283x over previous
#include <cuda_runtime.h>

#define NBLK 2048
#define TPB  256
#define NWARP (TPB / 32)
static constexpr int BATCH = 16777216;   // 2^24
// per-thread float4 iterations: (BATCH/4)/(NBLK*TPB) == 8 exactly

// Deterministic per-block partials: [0..3]=sums(normal,elev,hyper1,crisis), [4]=total
__device__ float    g_sums[5][NBLK];
__device__ unsigned g_cnts[4][NBLK];    // counts(normal,elev,hyper1,crisis)
__device__ unsigned g_ticket;           // zero-init; last block resets each launch

__device__ __forceinline__ float warp_red_f(float v) {
#pragma unroll
    for (int o = 16; o; o >>= 1) v += __shfl_down_sync(0xffffffffu, v, o);
    return v;
}
__device__ __forceinline__ unsigned warp_red_u(unsigned v) {
#pragma unroll
    for (int o = 16; o; o >>= 1) v += __shfl_down_sync(0xffffffffu, v, o);
    return v;
}

__global__ __launch_bounds__(TPB, 4) void amp_fused(
    const float4* __restrict__ dbp,
    const float4* __restrict__ sbp,
    const float4* __restrict__ dt,
    const float4* __restrict__ st,
    float* __restrict__ out)
{
    float tot = 0.f;                       // total per_elem sum (exhaustive cats)
    float s0 = 0.f, s1 = 0.f, s2 = 0.f, s4 = 0.f;
    unsigned c0 = 0u, c1 = 0u, c2 = 0u, c4 = 0u;

    const int stride = NBLK * TPB;
    const int base   = blockIdx.x * TPB + threadIdx.x;

    // Double-buffered streaming loads: next iteration's 4 LDG.128 are issued
    // before processing the current one -> >=8 loads in flight per warp.
    float4 cS = __ldcs(st  + base);
    float4 cD = __ldcs(dt  + base);
    float4 cP = __ldcs(dbp + base);
    float4 cQ = __ldcs(sbp + base);

#pragma unroll
    for (int k = 0; k < 8; k++) {
        float4 nS, nD, nP, nQ;
        if (k < 7) {
            const int ni = base + (k + 1) * stride;
            nS = __ldcs(st  + ni);
            nD = __ldcs(dt  + ni);
            nP = __ldcs(dbp + ni);
            nQ = __ldcs(sbp + ni);
        }

        const float sa[4] = {cS.x, cS.y, cS.z, cS.w};
        const float da[4] = {cD.x, cD.y, cD.z, cD.w};
        const float pa[4] = {cP.x, cP.y, cP.z, cP.w};
        const float qa[4] = {cQ.x, cQ.y, cQ.z, cQ.w};

#pragma unroll
        for (int j = 0; j < 4; j++) {
            const float s  = sa[j];
            const float d  = da[j];
            const float pd = pa[j];
            const float ps = qa[j];

            const float pe = 2.0f * __fdividef(fabsf(pd - d), fabsf(pd) + fabsf(d))
                           + 2.0f * __fdividef(fabsf(ps - s), fabsf(ps) + fabsf(s));

            // categories 0..3 are exclusive+exhaustive; cat3 derived later.
            // hyper1's exclusion of normal/elevated is implied by its ranges.
            const bool normal   = (s < 120.f) && (d < 80.f);
            const bool elevated = (s >= 120.f) && (s < 130.f) && (d < 80.f);
            const bool hyper1   = ((s >= 130.f) && (s < 140.f)) ||
                                  ((d >= 80.f) && (d < 90.f));
            const bool crisis   = (s > 180.f) || (d > 120.f);

            tot += pe;
            s0 += normal   ? pe : 0.f;  c0 += (unsigned)normal;
            s1 += elevated ? pe : 0.f;  c1 += (unsigned)elevated;
            s2 += hyper1   ? pe : 0.f;  c2 += (unsigned)hyper1;
            s4 += crisis   ? pe : 0.f;  c4 += (unsigned)crisis;
        }

        cS = nS; cD = nD; cP = nP; cQ = nQ;
    }

    // ---- block reduction ----
    __shared__ float    ws[5][NWARP];
    __shared__ unsigned wc[4][NWARP];
    const int lane = threadIdx.x & 31;
    const int warp = threadIdx.x >> 5;

    float    rs[5] = {s0, s1, s2, s4, tot};
    unsigned rc[4] = {c0, c1, c2, c4};
#pragma unroll
    for (int m = 0; m < 5; m++) {
        const float fs = warp_red_f(rs[m]);
        if (lane == 0) ws[m][warp] = fs;
    }
#pragma unroll
    for (int m = 0; m < 4; m++) {
        const unsigned uc = warp_red_u(rc[m]);
        if (lane == 0) wc[m][warp] = uc;
    }
    __syncthreads();

    if (warp == 0) {
#pragma unroll
        for (int m = 0; m < 5; m++) {
            float fs = (lane < NWARP) ? ws[m][lane] : 0.f;
#pragma unroll
            for (int o = NWARP / 2; o; o >>= 1)
                fs += __shfl_down_sync(0xffffffffu, fs, o);
            if (lane == 0) g_sums[m][blockIdx.x] = fs;
        }
#pragma unroll
        for (int m = 0; m < 4; m++) {
            unsigned uc = (lane < NWARP) ? wc[m][lane] : 0u;
#pragma unroll
            for (int o = NWARP / 2; o; o >>= 1)
                uc += __shfl_down_sync(0xffffffffu, uc, o);
            if (lane == 0) g_cnts[m][blockIdx.x] = uc;
        }
    }

    // ---- last-block finalize ----
    __shared__ bool s_last;
    __threadfence();
    __syncthreads();
    if (threadIdx.x == 0)
        s_last = (atomicAdd(&g_ticket, 1u) == (unsigned)(NBLK - 1));
    __syncthreads();
    if (!s_last) return;

    __threadfence();

    float    fs5[5] = {0.f, 0.f, 0.f, 0.f, 0.f};
    unsigned fc4[4] = {0u, 0u, 0u, 0u};
#pragma unroll
    for (int k = 0; k < NBLK / TPB; k++) {
        const int b = threadIdx.x + k * TPB;
#pragma unroll
        for (int m = 0; m < 5; m++) fs5[m] += g_sums[m][b];
#pragma unroll
        for (int m = 0; m < 4; m++) fc4[m] += g_cnts[m][b];
    }

    __shared__ float    fsum[5];
    __shared__ unsigned fcnt[4];
#pragma unroll
    for (int m = 0; m < 5; m++) {
        const float fs = warp_red_f(fs5[m]);
        if (lane == 0) ws[m][warp] = fs;
    }
#pragma unroll
    for (int m = 0; m < 4; m++) {
        const unsigned uc = warp_red_u(fc4[m]);
        if (lane == 0) wc[m][warp] = uc;
    }
    __syncthreads();

    if (warp == 0) {
#pragma unroll
        for (int m = 0; m < 5; m++) {
            float fs = (lane < NWARP) ? ws[m][lane] : 0.f;
#pragma unroll
            for (int o = NWARP / 2; o; o >>= 1)
                fs += __shfl_down_sync(0xffffffffu, fs, o);
            if (lane == 0) fsum[m] = fs;
        }
#pragma unroll
        for (int m = 0; m < 4; m++) {
            unsigned uc = (lane < NWARP) ? wc[m][lane] : 0u;
#pragma unroll
            for (int o = NWARP / 2; o; o >>= 1)
                uc += __shfl_down_sync(0xffffffffu, uc, o);
            if (lane == 0) fcnt[m] = uc;
        }
    }
    __syncthreads();

    if (threadIdx.x == 0) {
        // reconstruct category 3 (hyper2) from exhaustiveness
        float S[5];
        float C[5];
        S[0] = fsum[0];  C[0] = (float)fcnt[0];
        S[1] = fsum[1];  C[1] = (float)fcnt[1];
        S[2] = fsum[2];  C[2] = (float)fcnt[2];
        S[3] = fsum[4] - fsum[0] - fsum[1] - fsum[2];
        C[3] = (float)((unsigned)BATCH - fcnt[0] - fcnt[1] - fcnt[2]);
        S[4] = fsum[3];  C[4] = (float)fcnt[3];

        float rst = 0.f, m_rst = 0.f, mask_cnt = 0.f;
#pragma unroll
        for (int m = 0; m < 5; m++) {
            const float c = C[m];
            const float w = sqrtf(logf((float)BATCH / fmaxf(c, 1.0f)));
            const float Sw = S[m] * w;
            if (c > 0.f) {
                m_rst = (m_rst + Sw) / c / 2.0f;
                rst += m_rst;
                mask_cnt += 1.0f;
            }
        }
        out[0] = (mask_cnt == 0.f) ? (rst / 5.0f) : (rst / mask_cnt);
        g_ticket = 0u;   // reset for next graph replay
    }
}

extern "C" void kernel_launch(void* const* d_in, const int* in_sizes, int n_in,
                              void* d_out, int out_size)
{
    // metadata order: dbp_pred, sbp_pred, mbp_pred, d, s, m
    const float* dbp = (const float*)d_in[0];
    const float* sbp = (const float*)d_in[1];
    const float* dt  = (const float*)d_in[3];
    const float* st  = (const float*)d_in[4];

    amp_fused<<<NBLK, TPB>>>((const float4*)dbp, (const float4*)sbp,
                             (const float4*)dt,  (const float4*)st,
                             (float*)d_out);
}

// round 4
// speedup vs baseline: 1.1755x; 1.0413x over previous
#include <cuda_runtime.h>

#define NBLK 2048
#define TPB  256
#define NWARP (TPB / 32)
static constexpr int BATCH = 16777216;   // 2^24
// per-thread float4 iterations: (BATCH/4)/(NBLK*TPB) == 8 exactly

// 9 deterministic per-block partials:
// [0]=tot, [1..4]=sums(normal,elev,hyper1,crisis), [5..8]=counts(same, as floats)
__device__ float    g_part[9][NBLK];
__device__ unsigned g_ticket;            // zero-init; last block resets each launch

__device__ __forceinline__ float warp_red_f(float v) {
#pragma unroll
    for (int o = 16; o; o >>= 1) v += __shfl_down_sync(0xffffffffu, v, o);
    return v;
}

// Per-element: compute half-SMAPE sum, classify, accumulate with @p-guarded adds.
// Float constants: 80=0f42A00000 90=0f42B40000 120=0f42F00000 130=0f43020000
//                  140=0f430C0000 180=0f43340000 1.0=0f3F800000
__device__ __forceinline__ void accum_elem(
    const float s, const float d, const float pd, const float ps,
    float& tot, float& s0, float& s1, float& s2, float& s4,
    float& c0, float& c1, float& c2, float& c4)
{
    // pe WITHOUT the 2.0 factor (applied once in the finalize)
    const float pe = __fdividef(fabsf(pd - d), fabsf(pd) + fabsf(d))
                   + __fdividef(fabsf(ps - s), fabsf(ps) + fabsf(s));

    asm("{\n\t"
        ".reg .pred pd80, pn, q, pel, ps130, h1a, h1b, ph, pcd, pc;\n\t"
        "setp.lt.f32      pd80, %11, 0f42A00000;\n\t"          // d < 80
        "setp.lt.and.f32  pn,   %10, 0f42F00000, pd80;\n\t"    // normal = s<120 & d<80
        "setp.lt.and.f32  q,    %10, 0f43020000, pd80;\n\t"    // q = s<130 & d<80
        "xor.pred         pel,  q, pn;\n\t"                     // elevated = q & !normal
        "setp.ge.f32      ps130,%10, 0f43020000;\n\t"          // s >= 130
        "setp.lt.and.f32  h1a,  %10, 0f430C0000, ps130;\n\t"   // 130<=s<140
        "setp.lt.and.f32  h1b,  %11, 0f42B40000, !pd80;\n\t"   // 80<=d<90
        "or.pred          ph,   h1a, h1b;\n\t"                  // hyper1
        "setp.gt.f32      pcd,  %11, 0f42F00000;\n\t"          // d > 120
        "setp.gt.or.f32   pc,   %10, 0f43340000, pcd;\n\t"     // crisis = s>180 | d>120
        "     add.f32 %0, %0, %9;\n\t"
        "@pn  add.f32 %1, %1, %9;\n\t"
        "@pn  add.f32 %5, %5, 0f3F800000;\n\t"
        "@pel add.f32 %2, %2, %9;\n\t"
        "@pel add.f32 %6, %6, 0f3F800000;\n\t"
        "@ph  add.f32 %3, %3, %9;\n\t"
        "@ph  add.f32 %7, %7, 0f3F800000;\n\t"
        "@pc  add.f32 %4, %4, %9;\n\t"
        "@pc  add.f32 %8, %8, 0f3F800000;\n\t"
        "}"
        : "+f"(tot), "+f"(s0), "+f"(s1), "+f"(s2), "+f"(s4),
          "+f"(c0), "+f"(c1), "+f"(c2), "+f"(c4)
        : "f"(pe), "f"(s), "f"(d));
}

__global__ __launch_bounds__(TPB, 5) void amp_fused(
    const float4* __restrict__ dbp,
    const float4* __restrict__ sbp,
    const float4* __restrict__ dt,
    const float4* __restrict__ st,
    float* __restrict__ out)
{
    float tot = 0.f;
    float s0 = 0.f, s1 = 0.f, s2 = 0.f, s4 = 0.f;
    float c0 = 0.f, c1 = 0.f, c2 = 0.f, c4 = 0.f;

    const int stride = NBLK * TPB;
    const int base   = blockIdx.x * TPB + threadIdx.x;

    // Double-buffered streaming loads: next iteration's 4 LDG.128 issued
    // before consuming the current one.
    float4 cS = __ldcs(st  + base);
    float4 cD = __ldcs(dt  + base);
    float4 cP = __ldcs(dbp + base);
    float4 cQ = __ldcs(sbp + base);

#pragma unroll
    for (int k = 0; k < 8; k++) {
        float4 nS, nD, nP, nQ;
        if (k < 7) {
            const int ni = base + (k + 1) * stride;
            nS = __ldcs(st  + ni);
            nD = __ldcs(dt  + ni);
            nP = __ldcs(dbp + ni);
            nQ = __ldcs(sbp + ni);
        }

        accum_elem(cS.x, cD.x, cP.x, cQ.x, tot, s0, s1, s2, s4, c0, c1, c2, c4);
        accum_elem(cS.y, cD.y, cP.y, cQ.y, tot, s0, s1, s2, s4, c0, c1, c2, c4);
        accum_elem(cS.z, cD.z, cP.z, cQ.z, tot, s0, s1, s2, s4, c0, c1, c2, c4);
        accum_elem(cS.w, cD.w, cP.w, cQ.w, tot, s0, s1, s2, s4, c0, c1, c2, c4);

        cS = nS; cD = nD; cP = nP; cQ = nQ;
    }

    // ---- block reduction (9 float lanes) ----
    __shared__ float ws[9][NWARP];
    const int lane = threadIdx.x & 31;
    const int warp = threadIdx.x >> 5;

    float rs[9] = {tot, s0, s1, s2, s4, c0, c1, c2, c4};
#pragma unroll
    for (int m = 0; m < 9; m++) {
        const float fs = warp_red_f(rs[m]);
        if (lane == 0) ws[m][warp] = fs;
    }
    __syncthreads();

    if (warp == 0) {
#pragma unroll
        for (int m = 0; m < 9; m++) {
            float fs = (lane < NWARP) ? ws[m][lane] : 0.f;
#pragma unroll
            for (int o = NWARP / 2; o; o >>= 1)
                fs += __shfl_down_sync(0xffffffffu, fs, o);
            if (lane == 0) g_part[m][blockIdx.x] = fs;
        }
    }

    // ---- last-block finalize ----
    __shared__ bool s_last;
    __threadfence();
    __syncthreads();
    if (threadIdx.x == 0)
        s_last = (atomicAdd(&g_ticket, 1u) == (unsigned)(NBLK - 1));
    __syncthreads();
    if (!s_last) return;

    __threadfence();

    float f9[9] = {0.f, 0.f, 0.f, 0.f, 0.f, 0.f, 0.f, 0.f, 0.f};
#pragma unroll
    for (int k = 0; k < NBLK / TPB; k++) {
        const int b = threadIdx.x + k * TPB;
#pragma unroll
        for (int m = 0; m < 9; m++) f9[m] += g_part[m][b];
    }

    __shared__ float fin[9];
#pragma unroll
    for (int m = 0; m < 9; m++) {
        const float fs = warp_red_f(f9[m]);
        if (lane == 0) ws[m][warp] = fs;
    }
    __syncthreads();

    if (warp == 0) {
#pragma unroll
        for (int m = 0; m < 9; m++) {
            float fs = (lane < NWARP) ? ws[m][lane] : 0.f;
#pragma unroll
            for (int o = NWARP / 2; o; o >>= 1)
                fs += __shfl_down_sync(0xffffffffu, fs, o);
            if (lane == 0) fin[m] = fs;
        }
    }
    __syncthreads();

    if (threadIdx.x == 0) {
        // reconstruct hyper2 from exhaustiveness of categories 0..3;
        // restore the 2.0 SMAPE factor here.
        float S[5], C[5];
        S[0] = 2.0f * fin[1];                              C[0] = fin[5];
        S[1] = 2.0f * fin[2];                              C[1] = fin[6];
        S[2] = 2.0f * fin[3];                              C[2] = fin[7];
        S[3] = 2.0f * (fin[0] - fin[1] - fin[2] - fin[3]); C[3] = (float)BATCH - fin[5] - fin[6] - fin[7];
        S[4] = 2.0f * fin[4];                              C[4] = fin[8];

        float rst = 0.f, m_rst = 0.f, mask_cnt = 0.f;
#pragma unroll
        for (int m = 0; m < 5; m++) {
            const float c = C[m];
            const float w = sqrtf(logf((float)BATCH / fmaxf(c, 1.0f)));
            const float Sw = S[m] * w;
            if (c > 0.f) {
                m_rst = (m_rst + Sw) / c / 2.0f;
                rst += m_rst;
                mask_cnt += 1.0f;
            }
        }
        out[0] = (mask_cnt == 0.f) ? (rst / 5.0f) : (rst / mask_cnt);
        g_ticket = 0u;   // reset for next graph replay
    }
}

extern "C" void kernel_launch(void* const* d_in, const int* in_sizes, int n_in,
                              void* d_out, int out_size)
{
    // metadata order: dbp_pred, sbp_pred, mbp_pred, d, s, m
    const float* dbp = (const float*)d_in[0];
    const float* sbp = (const float*)d_in[1];
    const float* dt  = (const float*)d_in[3];
    const float* st  = (const float*)d_in[4];

    amp_fused<<<NBLK, TPB>>>((const float4*)dbp, (const float4*)sbp,
                             (const float4*)dt,  (const float4*)st,
                             (float*)d_out);
}